// round 1
// baseline (speedup 1.0000x reference)
#include <cuda_runtime.h>

#define LEAK 0.01f

// ---------------- scratch (device globals; no allocation allowed) ----------
static __device__ float g_t [3145728];              // conv temp   [4,192,64,64]
static __device__ float g_f1[3145728];              // theta branch out
static __device__ float g_f2[3145728];              // phi branch out
static __device__ float g_P [67108864];             // corr        [4,4096,4096]
static __device__ float g_V [9437184];              // fused V     [4,4096,576]
static __device__ float g_O [9437184];              // attention O [4,4096,576]

// ---------------- conv3x3 + bias + leaky-relu (+ optional residual) --------
// grid: (64 spatial tiles of 8x8, 3 oc-groups of 64, 4 batch). block: 256.
__global__ void conv3x3_lrelu(const float* __restrict__ x,
                              const float* __restrict__ w,
                              const float* __restrict__ bias,
                              const float* __restrict__ res,
                              float* __restrict__ y)
{
    __shared__ float s_in[16][10][10];   // 16 ic x (8+2)x(8+2) halo tile
    __shared__ float s_w[9][16][64];     // [tap][ic][oc]

    const int b    = blockIdx.z;
    const int oc0  = blockIdx.y * 64;
    const int tile = blockIdx.x;
    const int th0  = (tile >> 3) << 3;
    const int tw0  = (tile & 7) << 3;
    const int tid  = threadIdx.x;
    const int ocq  = tid & 15;          // 16 oc groups of 4
    const int pxq  = tid >> 4;          // 16 pixel groups of 4
    const int row  = pxq >> 1;          // 0..7
    const int cb   = (pxq & 1) << 2;    // 0 or 4

    float acc[4][4];
#pragma unroll
    for (int i = 0; i < 4; i++)
#pragma unroll
        for (int j = 0; j < 4; j++) acc[i][j] = 0.f;

    for (int ic0 = 0; ic0 < 192; ic0 += 16) {
        // input tile with zero halo
        for (int i = tid; i < 1600; i += 256) {
            int ic = i / 100; int r = i % 100;
            int yy = r / 10;  int xx = r % 10;
            int gh = th0 + yy - 1, gw = tw0 + xx - 1;
            float v = 0.f;
            if (gh >= 0 && gh < 64 && gw >= 0 && gw < 64)
                v = x[((b * 192 + ic0 + ic) * 64 + gh) * 64 + gw];
            s_in[ic][yy][xx] = v;
        }
        // weights, transposed so 4 consecutive oc vectorize
        for (int i = tid; i < 9216; i += 256) {
            int oc = i / 144; int r = i % 144;
            int ic = r / 9;   int tap = r % 9;
            s_w[tap][ic][oc] = w[((oc0 + oc) * 192 + ic0 + ic) * 9 + tap];
        }
        __syncthreads();

#pragma unroll 4
        for (int ic = 0; ic < 16; ic++) {
#pragma unroll
            for (int ky = 0; ky < 3; ky++) {
#pragma unroll
                for (int kx = 0; kx < 3; kx++) {
                    const float4 wv = *(const float4*)&s_w[ky * 3 + kx][ic][ocq * 4];
#pragma unroll
                    for (int p = 0; p < 4; p++) {
                        float iv = s_in[ic][row + ky][cb + p + kx];
                        acc[0][p] += wv.x * iv;
                        acc[1][p] += wv.y * iv;
                        acc[2][p] += wv.z * iv;
                        acc[3][p] += wv.w * iv;
                    }
                }
            }
        }
        __syncthreads();
    }

    const int gh = th0 + row;
    const int gw = tw0 + cb;
#pragma unroll
    for (int o = 0; o < 4; o++) {
        const int oc = oc0 + ocq * 4 + o;
        const float bv = bias[oc];
        const size_t base = (((size_t)b * 192 + oc) * 64 + gh) * 64 + gw;
        float4 rv = make_float4(0.f, 0.f, 0.f, 0.f);
        if (res) rv = *(const float4*)&res[base];
        float v0 = acc[o][0] + bv; v0 = (v0 > 0.f ? v0 : LEAK * v0) + rv.x;
        float v1 = acc[o][1] + bv; v1 = (v1 > 0.f ? v1 : LEAK * v1) + rv.y;
        float v2 = acc[o][2] + bv; v2 = (v2 > 0.f ? v2 : LEAK * v2) + rv.z;
        float v3 = acc[o][3] + bv; v3 = (v3 > 0.f ? v3 : LEAK * v3) + rv.w;
        *(float4*)&y[base] = make_float4(v0, v1, v2, v3);
    }
}

// ---------------- S = f1^T f2  (per batch 4096x4096, K=192) ----------------
// 128x128 tile, 256 threads, 8x8 per thread. grid (32,32,4).
__global__ void gemm_corr(const float* __restrict__ A, const float* __restrict__ B)
{
    __shared__ float As[16][128];
    __shared__ float Bs[16][128];
    const int b  = blockIdx.z;
    const int m0 = blockIdx.y * 128;
    const int n0 = blockIdx.x * 128;
    const float* Ab = A + (size_t)b * 192 * 4096;
    const float* Bb = B + (size_t)b * 192 * 4096;
    float* Pb = g_P + (size_t)b * 4096 * 4096;

    const int tid = threadIdx.x;
    const int tx  = tid & 15, ty = tid >> 4;
    const int lr  = tid >> 5;
    const int lc  = (tid & 31) << 2;

    float acc[8][8];
#pragma unroll
    for (int i = 0; i < 8; i++)
#pragma unroll
        for (int j = 0; j < 8; j++) acc[i][j] = 0.f;

    for (int c0 = 0; c0 < 192; c0 += 16) {
        *(float4*)&As[lr][lc]     = *(const float4*)&Ab[(size_t)(c0 + lr) * 4096 + m0 + lc];
        *(float4*)&As[lr + 8][lc] = *(const float4*)&Ab[(size_t)(c0 + lr + 8) * 4096 + m0 + lc];
        *(float4*)&Bs[lr][lc]     = *(const float4*)&Bb[(size_t)(c0 + lr) * 4096 + n0 + lc];
        *(float4*)&Bs[lr + 8][lc] = *(const float4*)&Bb[(size_t)(c0 + lr + 8) * 4096 + n0 + lc];
        __syncthreads();
#pragma unroll
        for (int c = 0; c < 16; c++) {
            float4 a0 = *(const float4*)&As[c][ty << 2];
            float4 a1 = *(const float4*)&As[c][64 + (ty << 2)];
            float4 b0 = *(const float4*)&Bs[c][tx << 2];
            float4 b1 = *(const float4*)&Bs[c][64 + (tx << 2)];
            float av[8] = {a0.x, a0.y, a0.z, a0.w, a1.x, a1.y, a1.z, a1.w};
            float bv[8] = {b0.x, b0.y, b0.z, b0.w, b1.x, b1.y, b1.z, b1.w};
#pragma unroll
            for (int i = 0; i < 8; i++)
#pragma unroll
                for (int j = 0; j < 8; j++)
                    acc[i][j] += av[i] * bv[j];
        }
        __syncthreads();
    }
#pragma unroll
    for (int i = 0; i < 8; i++) {
        int q = m0 + ((i < 4) ? (ty << 2) + i : 64 + (ty << 2) + i - 4);
        float4 v0 = make_float4(acc[i][0], acc[i][1], acc[i][2], acc[i][3]);
        float4 v1 = make_float4(acc[i][4], acc[i][5], acc[i][6], acc[i][7]);
        *(float4*)&Pb[(size_t)q * 4096 + n0 + (tx << 2)]      = v0;
        *(float4*)&Pb[(size_t)q * 4096 + n0 + 64 + (tx << 2)] = v1;
    }
}

// ---------------- row softmax over 4096 keys (one block per row) -----------
__global__ void softmax_rows()
{
    __shared__ float s[4096];
    __shared__ float red[256];
    float* p = g_P + (size_t)blockIdx.x * 4096;
    const int tid = threadIdx.x;

    float m = -1e30f;
    for (int i = tid; i < 4096; i += 256) { float v = p[i]; s[i] = v; m = fmaxf(m, v); }
    red[tid] = m; __syncthreads();
    for (int o = 128; o > 0; o >>= 1) {
        if (tid < o) red[tid] = fmaxf(red[tid], red[tid + o]);
        __syncthreads();
    }
    m = red[0];
    __syncthreads();

    float sum = 0.f;
    for (int i = tid; i < 4096; i += 256) { float e = __expf(s[i] - m); s[i] = e; sum += e; }
    red[tid] = sum; __syncthreads();
    for (int o = 128; o > 0; o >>= 1) {
        if (tid < o) red[tid] += red[tid + o];
        __syncthreads();
    }
    const float inv = 1.0f / red[0];
    for (int i = tid; i < 4096; i += 256) p[i] = s[i] * inv;
}

// ---------------- fused value matrix V[b][k][576] ---------------------------
// V[:,0:192]=ref, V[:,192:384]=upsample2(o1)/4, V[:,384:576]=upsample4(o2)/16
__global__ void build_V(const float* __restrict__ ref,
                        const float* __restrict__ o1,
                        const float* __restrict__ o2)
{
    const int idx = blockIdx.x * 256 + threadIdx.x;       // < 9437184 exact
    const int v = idx % 576;
    const int k = (idx / 576) & 4095;
    const int b = idx / (576 * 4096);
    const int h = k >> 6, w = k & 63;
    float val;
    if (v < 192)
        val = ref[(((size_t)b * 192 + v) << 12) + k];
    else if (v < 384)
        val = 0.25f   * o1[(((size_t)b * 192 + (v - 192)) << 10) + ((h >> 1) << 5) + (w >> 1)];
    else
        val = 0.0625f * o2[(((size_t)b * 192 + (v - 384)) << 8)  + ((h >> 2) << 4) + (w >> 2)];
    g_V[idx] = val;
}

// ---------------- O = P @ V  (per batch 4096x576, K=4096) ------------------
// 128x64 tile, 256 threads, 8x4 per thread. grid (9,32,4). N=576=9*64 exact.
__global__ void gemm_out()
{
    __shared__ float As[16 * 132];       // transposed [k][m], padded stride 132
    __shared__ float Bs[16][64];
    const int b  = blockIdx.z;
    const int m0 = blockIdx.y * 128;
    const int n0 = blockIdx.x * 64;
    const float* Pb = g_P + (size_t)b * 4096 * 4096;
    const float* Vb = g_V + (size_t)b * 4096 * 576;
    float* Ob = g_O + (size_t)b * 4096 * 576;

    const int tid = threadIdx.x;
    const int tx  = tid & 15, ty = tid >> 4;
    const int am  = tid >> 2;           // 0..63
    const int ak  = (tid & 3) << 2;     // 0,4,8,12
    const int br  = tid >> 4;           // 0..15
    const int bc  = (tid & 15) << 2;    // 0..60

    float acc[8][4];
#pragma unroll
    for (int i = 0; i < 8; i++)
#pragma unroll
        for (int j = 0; j < 4; j++) acc[i][j] = 0.f;

    for (int k0 = 0; k0 < 4096; k0 += 16) {
        float4 a0 = *(const float4*)&Pb[(size_t)(m0 + am) * 4096 + k0 + ak];
        float4 a1 = *(const float4*)&Pb[(size_t)(m0 + am + 64) * 4096 + k0 + ak];
        As[(ak + 0) * 132 + am] = a0.x;
        As[(ak + 1) * 132 + am] = a0.y;
        As[(ak + 2) * 132 + am] = a0.z;
        As[(ak + 3) * 132 + am] = a0.w;
        As[(ak + 0) * 132 + am + 64] = a1.x;
        As[(ak + 1) * 132 + am + 64] = a1.y;
        As[(ak + 2) * 132 + am + 64] = a1.z;
        As[(ak + 3) * 132 + am + 64] = a1.w;
        *(float4*)&Bs[br][bc] = *(const float4*)&Vb[(size_t)(k0 + br) * 576 + n0 + bc];
        __syncthreads();
#pragma unroll
        for (int c = 0; c < 16; c++) {
            float4 a0v = *(const float4*)&As[c * 132 + (ty << 2)];
            float4 a1v = *(const float4*)&As[c * 132 + 64 + (ty << 2)];
            float4 bv  = *(const float4*)&Bs[c][tx << 2];
            float av[8] = {a0v.x, a0v.y, a0v.z, a0v.w, a1v.x, a1v.y, a1v.z, a1v.w};
            float bb[4] = {bv.x, bv.y, bv.z, bv.w};
#pragma unroll
            for (int i = 0; i < 8; i++)
#pragma unroll
                for (int j = 0; j < 4; j++)
                    acc[i][j] += av[i] * bb[j];
        }
        __syncthreads();
    }
#pragma unroll
    for (int i = 0; i < 8; i++) {
        int q = m0 + ((i < 4) ? (ty << 2) + i : 64 + (ty << 2) + i - 4);
        *(float4*)&Ob[(size_t)q * 576 + n0 + (tx << 2)] =
            make_float4(acc[i][0], acc[i][1], acc[i][2], acc[i][3]);
    }
}

// ---------------- final outputs: transpose + query-grid pooling ------------
__global__ void write_out(float* __restrict__ out)
{
    const int idx = blockIdx.x * 256 + threadIdx.x;       // < 4128768 exact
    if (idx < 3145728) {                                  // out0 [4,192,64,64]
        int b = idx / (192 * 4096);
        int c = (idx / 4096) % 192;
        int p = idx & 4095;
        out[idx] = g_O[((size_t)(b * 4096 + p)) * 576 + c];
    } else if (idx < 3932160) {                           // out1 [4,192,32,32]
        int j = idx - 3145728;
        int b = j / (192 * 1024);
        int c = (j / 1024) % 192;
        int p = j & 1023;
        int h2 = p >> 5, w2 = p & 31;
        float s = 0.f;
#pragma unroll
        for (int dy = 0; dy < 2; dy++)
#pragma unroll
            for (int dx = 0; dx < 2; dx++) {
                int q = (2 * h2 + dy) * 64 + 2 * w2 + dx;
                s += g_O[((size_t)(b * 4096 + q)) * 576 + 192 + c];
            }
        out[idx] = 0.25f * s;
    } else {                                              // out2 [4,192,16,16]
        int j = idx - 3932160;
        int b = j / (192 * 256);
        int c = (j / 256) % 192;
        int p = j & 255;
        int h4 = p >> 4, w4 = p & 15;
        float s = 0.f;
#pragma unroll
        for (int dy = 0; dy < 4; dy++)
#pragma unroll
            for (int dx = 0; dx < 4; dx++) {
                int q = (4 * h4 + dy) * 64 + 4 * w4 + dx;
                s += g_O[((size_t)(b * 4096 + q)) * 576 + 384 + c];
            }
        out[idx] = 0.0625f * s;
    }
}

// ---------------------------------------------------------------------------
extern "C" void kernel_launch(void* const* d_in, const int* in_sizes, int n_in,
                              void* d_out, int out_size)
{
    (void)in_sizes; (void)n_in; (void)out_size;
    const float* fd1 = (const float*)d_in[0];
    const float* fd2 = (const float*)d_in[1];
    const float* ref = (const float*)d_in[2];
    const float* o1  = (const float*)d_in[3];
    const float* o2  = (const float*)d_in[4];
    const float* tw1 = (const float*)d_in[5];
    const float* tb1 = (const float*)d_in[6];
    const float* tw2 = (const float*)d_in[7];
    const float* tb2 = (const float*)d_in[8];
    const float* pw1 = (const float*)d_in[9];
    const float* pb1 = (const float*)d_in[10];
    const float* pw2 = (const float*)d_in[11];
    const float* pb2 = (const float*)d_in[12];
    float* out = (float*)d_out;

    float *t, *f1, *f2;
    cudaGetSymbolAddress((void**)&t,  g_t);
    cudaGetSymbolAddress((void**)&f1, g_f1);
    cudaGetSymbolAddress((void**)&f2, g_f2);

    dim3 cgrid(64, 3, 4);
    conv3x3_lrelu<<<cgrid, 256>>>(fd1, tw1, tb1, nullptr, t);
    conv3x3_lrelu<<<cgrid, 256>>>(t,   tw2, tb2, fd1,     f1);
    conv3x3_lrelu<<<cgrid, 256>>>(fd2, pw1, pb1, nullptr, t);
    conv3x3_lrelu<<<cgrid, 256>>>(t,   pw2, pb2, fd2,     f2);

    gemm_corr<<<dim3(32, 32, 4), 256>>>(f1, f2);
    softmax_rows<<<16384, 256>>>();
    build_V<<<36864, 256>>>(ref, o1, o2);
    gemm_out<<<dim3(9, 32, 4), 256>>>();
    write_out<<<16128, 256>>>(out);
}

// round 4
// speedup vs baseline: 1.8148x; 1.8148x over previous
#include <cuda_runtime.h>

#define LEAK 0.01f

// ---------------- scratch (device globals; no allocation allowed) ----------
static __device__ float g_wt[1327104];              // repacked weights 4x[1728][192]
static __device__ float g_t [6291456];              // layer1 out, 2 branches [2][4][192][4096]
static __device__ float g_f1[3145728];              // theta branch out [4][192][4096]
static __device__ float g_f2[3145728];              // phi branch out
static __device__ float g_P [67108864];             // corr        [4][4096][4096]
static __device__ float g_P1[16777216];             // q-pooled    [4][1024][4096]
static __device__ float g_P2[4194304];              // q-pooled^2  [4][256][4096]
static __device__ float g_V [9437184];              // fused V     [4][4096][576]

// ---------------- f32x2 packed helpers -------------------------------------
__device__ __forceinline__ void fma2(unsigned long long& d,
                                     unsigned long long a, unsigned long long b)
{
    asm("fma.rn.f32x2 %0, %1, %2, %0;" : "+l"(d) : "l"(a), "l"(b));
}
__device__ __forceinline__ unsigned long long dup2(float x)
{
    unsigned long long d;
    asm("mov.b64 %0, {%1, %2};" : "=l"(d) : "f"(x), "f"(x));
    return d;
}
__device__ __forceinline__ float2 unpk(unsigned long long v)
{
    float2 f;
    asm("mov.b64 {%0, %1}, %2;" : "=f"(f.x), "=f"(f.y) : "l"(v));
    return f;
}
__device__ __forceinline__ float4 pair4(unsigned long long a, unsigned long long b)
{
    float2 x = unpk(a), y = unpk(b);
    return make_float4(x.x, x.y, y.x, y.y);
}

// ---------------- weight repack: w[oc][ic][3][3] -> g_wt[s][tap*192+ic][oc] -
__global__ void repack_w(const float* __restrict__ w0, const float* __restrict__ w1,
                         const float* __restrict__ w2, const float* __restrict__ w3)
{
    int idx = blockIdx.x * 256 + threadIdx.x;           // < 1327104 exact
    int s   = idx / 331776;
    int r   = idx % 331776;
    int k   = r / 192;
    int oc  = r % 192;
    int tap = k / 192;
    int ic  = k % 192;
    const float* w = (s == 0) ? w0 : (s == 1) ? w1 : (s == 2) ? w2 : w3;
    g_wt[idx] = w[(oc * 192 + ic) * 9 + tap];
}

// ---------------- conv3x3 as implicit GEMM ---------------------------------
// y[oc][p] = leaky( sum_{tap,ic} x[ic][p+off(tap)] * wt[tap*192+ic][oc] + bias ) (+res)
// tile 128p x 64oc, 256 threads, per-thread 8p x 4oc via f32x2.
// grid (3, 32, 8): z = batch(0..3) | branch<<2
__global__ void __launch_bounds__(256, 2)
conv_gemm(const float* __restrict__ x0, const float* __restrict__ x1,
          const float* __restrict__ res0, const float* __restrict__ res1,
          int wslot0, int wslot1,
          const float* __restrict__ bias0, const float* __restrict__ bias1,
          float* __restrict__ y0, float* __restrict__ y1)
{
    __shared__ float As[16][128];
    __shared__ float Bs[16][64];

    const int b  = blockIdx.z & 3;
    const int br = blockIdx.z >> 2;
    const float* xb   = (br ? x1 : x0) + (size_t)b * 192 * 4096;
    const float* wt   = g_wt + (size_t)(br ? wslot1 : wslot0) * 331776;
    const float* bias = br ? bias1 : bias0;
    const float* resb = br ? res1 : res0;
    if (resb) resb += (size_t)b * 192 * 4096;
    float* yb = (br ? y1 : y0) + (size_t)b * 192 * 4096;

    const int m0 = blockIdx.y * 128;
    const int n0 = blockIdx.x * 64;
    const int tid = threadIdx.x;
    const int tx = tid & 15, ty = tid >> 4;

    // A-load mapping: 128 p x 16 k, each thread 8 scalars
    const int lp  = tid & 127;
    const int kk0 = (tid >> 7) * 8;
    const int gp  = m0 + lp;
    const int lh  = gp >> 6, lw = gp & 63;
    // B-load mapping
    const int br2 = tid >> 4;            // 0..15
    const int bc2 = (tid & 15) << 2;     // 0..60

    unsigned long long acc[4][4];
#pragma unroll
    for (int i = 0; i < 4; i++)
#pragma unroll
        for (int j = 0; j < 4; j++) acc[i][j] = 0ull;

#pragma unroll 1
    for (int tap = 0; tap < 9; tap++) {
        const int ky = tap / 3, kx = tap % 3;
        const int off = (ky - 1) * 64 + (kx - 1);
        const bool ok = (lh + ky - 1 >= 0) && (lh + ky - 1 < 64) &&
                        (lw + kx - 1 >= 0) && (lw + kx - 1 < 64);
        const float* srcA = xb + gp + off + (size_t)kk0 * 4096;
        const float* srcB = wt + (size_t)(tap * 192 + br2) * 192 + n0 + bc2;

#pragma unroll 1
        for (int ic0 = 0; ic0 < 192; ic0 += 16) {
#pragma unroll
            for (int kk = 0; kk < 8; kk++)
                As[kk0 + kk][lp] = ok ? __ldg(srcA + (size_t)(ic0 + kk) * 4096) : 0.f;
            *(float4*)&Bs[br2][bc2] = *(const float4*)(srcB + (size_t)ic0 * 192);
            __syncthreads();
#pragma unroll
            for (int c = 0; c < 16; c++) {
                ulonglong2 A0 = *(const ulonglong2*)&As[c][ty << 2];
                ulonglong2 A1 = *(const ulonglong2*)&As[c][64 + (ty << 2)];
                float4 bv = *(const float4*)&Bs[c][tx << 2];
                unsigned long long ap[4] = {A0.x, A0.y, A1.x, A1.y};
                unsigned long long bd[4] = {dup2(bv.x), dup2(bv.y), dup2(bv.z), dup2(bv.w)};
#pragma unroll
                for (int i = 0; i < 4; i++)
#pragma unroll
                    for (int j = 0; j < 4; j++)
                        fma2(acc[i][j], ap[i], bd[j]);
            }
            __syncthreads();
        }
    }

    // epilogue: bias + leaky (+res), store transposed y[oc][p], float4 along p
#pragma unroll
    for (int j = 0; j < 4; j++) {
        const int oc = n0 + (tx << 2) + j;
        const float bv = bias[oc];
        const size_t base = (size_t)oc * 4096 + m0 + (ty << 2);
        float4 v0 = pair4(acc[0][j], acc[1][j]);
        float4 v1 = pair4(acc[2][j], acc[3][j]);
        v0.x += bv; v0.y += bv; v0.z += bv; v0.w += bv;
        v1.x += bv; v1.y += bv; v1.z += bv; v1.w += bv;
        v0.x = v0.x > 0.f ? v0.x : LEAK * v0.x;
        v0.y = v0.y > 0.f ? v0.y : LEAK * v0.y;
        v0.z = v0.z > 0.f ? v0.z : LEAK * v0.z;
        v0.w = v0.w > 0.f ? v0.w : LEAK * v0.w;
        v1.x = v1.x > 0.f ? v1.x : LEAK * v1.x;
        v1.y = v1.y > 0.f ? v1.y : LEAK * v1.y;
        v1.z = v1.z > 0.f ? v1.z : LEAK * v1.z;
        v1.w = v1.w > 0.f ? v1.w : LEAK * v1.w;
        if (resb) {
            float4 r0 = *(const float4*)&resb[base];
            float4 r1 = *(const float4*)&resb[base + 64];
            v0.x += r0.x; v0.y += r0.y; v0.z += r0.z; v0.w += r0.w;
            v1.x += r1.x; v1.y += r1.y; v1.z += r1.z; v1.w += r1.w;
        }
        *(float4*)&yb[base]      = v0;
        *(float4*)&yb[base + 64] = v1;
    }
}

// ---------------- S = f1^T f2  (per batch 4096x4096, K=192) ----------------
// 128x128 tile, 256 threads, 8x8 per thread via f32x2. grid (32,32,4).
__global__ void __launch_bounds__(256, 2)
gemm_corr(const float* __restrict__ A, const float* __restrict__ B)
{
    __shared__ float As[16][128];
    __shared__ float Bs[16][128];
    const int b  = blockIdx.z;
    const int m0 = blockIdx.y * 128;
    const int n0 = blockIdx.x * 128;
    const float* Ab = A + (size_t)b * 192 * 4096;
    const float* Bb = B + (size_t)b * 192 * 4096;
    float* Pb = g_P + (size_t)b * 4096 * 4096;

    const int tid = threadIdx.x;
    const int tx  = tid & 15, ty = tid >> 4;
    const int lr  = tid >> 5;
    const int lc  = (tid & 31) << 2;

    unsigned long long acc[4][8];
#pragma unroll
    for (int i = 0; i < 4; i++)
#pragma unroll
        for (int j = 0; j < 8; j++) acc[i][j] = 0ull;

#pragma unroll 1
    for (int c0 = 0; c0 < 192; c0 += 16) {
        *(float4*)&As[lr][lc]     = *(const float4*)&Ab[(size_t)(c0 + lr) * 4096 + m0 + lc];
        *(float4*)&As[lr + 8][lc] = *(const float4*)&Ab[(size_t)(c0 + lr + 8) * 4096 + m0 + lc];
        *(float4*)&Bs[lr][lc]     = *(const float4*)&Bb[(size_t)(c0 + lr) * 4096 + n0 + lc];
        *(float4*)&Bs[lr + 8][lc] = *(const float4*)&Bb[(size_t)(c0 + lr + 8) * 4096 + n0 + lc];
        __syncthreads();
#pragma unroll
        for (int c = 0; c < 16; c++) {
            ulonglong2 A0 = *(const ulonglong2*)&As[c][ty << 2];
            ulonglong2 A1 = *(const ulonglong2*)&As[c][64 + (ty << 2)];
            float4 b0 = *(const float4*)&Bs[c][tx << 2];
            float4 b1 = *(const float4*)&Bs[c][64 + (tx << 2)];
            unsigned long long ap[4] = {A0.x, A0.y, A1.x, A1.y};
            unsigned long long bd[8] = {dup2(b0.x), dup2(b0.y), dup2(b0.z), dup2(b0.w),
                                        dup2(b1.x), dup2(b1.y), dup2(b1.z), dup2(b1.w)};
#pragma unroll
            for (int i = 0; i < 4; i++)
#pragma unroll
                for (int j = 0; j < 8; j++)
                    fma2(acc[i][j], ap[i], bd[j]);
        }
        __syncthreads();
    }

#pragma unroll
    for (int i2 = 0; i2 < 4; i2++) {
        float2 u[8];
#pragma unroll
        for (int j = 0; j < 8; j++) u[j] = unpk(acc[i2][j]);
        const int q = m0 + (ty << 2) + ((i2 & 1) << 1) + ((i2 >> 1) << 6);
        float4 lo0 = make_float4(u[0].x, u[1].x, u[2].x, u[3].x);
        float4 lo1 = make_float4(u[4].x, u[5].x, u[6].x, u[7].x);
        float4 hi0 = make_float4(u[0].y, u[1].y, u[2].y, u[3].y);
        float4 hi1 = make_float4(u[4].y, u[5].y, u[6].y, u[7].y);
        *(float4*)&Pb[(size_t)q * 4096 + n0 + (tx << 2)]            = lo0;
        *(float4*)&Pb[(size_t)q * 4096 + n0 + 64 + (tx << 2)]       = lo1;
        *(float4*)&Pb[(size_t)(q + 1) * 4096 + n0 + (tx << 2)]      = hi0;
        *(float4*)&Pb[(size_t)(q + 1) * 4096 + n0 + 64 + (tx << 2)] = hi1;
    }
}

// ---------------- row softmax over 4096 keys (one block per row) -----------
__global__ void softmax_rows()
{
    __shared__ float s[4096];
    __shared__ float red[256];
    float* p = g_P + (size_t)blockIdx.x * 4096;
    const int tid = threadIdx.x;

    float m = -1e30f;
    for (int i = tid; i < 4096; i += 256) { float v = p[i]; s[i] = v; m = fmaxf(m, v); }
    red[tid] = m; __syncthreads();
    for (int o = 128; o > 0; o >>= 1) {
        if (tid < o) red[tid] = fmaxf(red[tid], red[tid + o]);
        __syncthreads();
    }
    m = red[0];
    __syncthreads();

    float sum = 0.f;
    for (int i = tid; i < 4096; i += 256) { float e = __expf(s[i] - m); s[i] = e; sum += e; }
    red[tid] = sum; __syncthreads();
    for (int o = 128; o > 0; o >>= 1) {
        if (tid < o) red[tid] += red[tid + o];
        __syncthreads();
    }
    const float inv = 1.0f / red[0];
    for (int i = tid; i < 4096; i += 256) p[i] = s[i] * inv;
}

// ---------------- query-grid pooling of P ----------------------------------
__global__ void pool_P1()      // P1[b][q1][k] = avg of 4 query rows of P
{
    const int idx = blockIdx.x * 256 + threadIdx.x;   // < 4*1024*1024 (float4 units)
    const int b  = idx >> 20;
    const int q1 = (idx >> 10) & 1023;
    const int k4 = idx & 1023;
    const int h2 = q1 >> 5, w2 = q1 & 31;
    const int r  = (h2 * 2) * 64 + w2 * 2;
    const float4* base = (const float4*)(g_P + ((size_t)b * 4096 + r) * 4096) + k4;
    float4 a = base[0], c = base[1024], d = base[64 * 1024], e = base[65 * 1024];
    float4 o;
    o.x = 0.25f * (a.x + c.x + d.x + e.x);
    o.y = 0.25f * (a.y + c.y + d.y + e.y);
    o.z = 0.25f * (a.z + c.z + d.z + e.z);
    o.w = 0.25f * (a.w + c.w + d.w + e.w);
    ((float4*)(g_P1 + ((size_t)b * 1024 + q1) * 4096))[k4] = o;
}

__global__ void pool_P2()      // P2[b][q2][k] = avg of 4 rows of P1
{
    const int idx = blockIdx.x * 256 + threadIdx.x;   // < 4*256*1024
    const int b  = idx >> 18;
    const int q2 = (idx >> 10) & 255;
    const int k4 = idx & 1023;
    const int h4 = q2 >> 4, w4 = q2 & 15;
    const int r  = (h4 * 2) * 32 + w4 * 2;
    const float4* base = (const float4*)(g_P1 + ((size_t)b * 1024 + r) * 4096) + k4;
    float4 a = base[0], c = base[1024], d = base[32 * 1024], e = base[33 * 1024];
    float4 o;
    o.x = 0.25f * (a.x + c.x + d.x + e.x);
    o.y = 0.25f * (a.y + c.y + d.y + e.y);
    o.z = 0.25f * (a.z + c.z + d.z + e.z);
    o.w = 0.25f * (a.w + c.w + d.w + e.w);
    ((float4*)(g_P2 + ((size_t)b * 256 + q2) * 4096))[k4] = o;
}

// ---------------- fused value matrix V[b][k][576] --------------------------
__global__ void build_V(const float* __restrict__ ref,
                        const float* __restrict__ o1,
                        const float* __restrict__ o2)
{
    const int idx = blockIdx.x * 256 + threadIdx.x;       // < 9437184 exact
    const int v = idx % 576;
    const int k = (idx / 576) & 4095;
    const int b = idx / (576 * 4096);
    const int h = k >> 6, w = k & 63;
    float val;
    if (v < 192)
        val = ref[(((size_t)b * 192 + v) << 12) + k];
    else if (v < 384)
        val = 0.25f   * o1[(((size_t)b * 192 + (v - 192)) << 10) + ((h >> 1) << 5) + (w >> 1)];
    else
        val = 0.0625f * o2[(((size_t)b * 192 + (v - 384)) << 8)  + ((h >> 2) << 4) + (w >> 2)];
    g_V[idx] = val;
}

// ---------------- combined PV GEMM -> final outputs ------------------------
// segmented grid.y: [0,32) out0 (P,4096), [32,40) out1 (P1,1024), [40,42) out2 (P2,256)
// tile 128q x 64c, writes out[b][c][q] directly (transposed, coalesced).
__global__ void __launch_bounds__(256, 2)
gemm_pv(float* __restrict__ out)
{
    __shared__ float As[16 * 132];
    __shared__ float Bs[16][64];

    const float* A; int M; int vofs; float* obase; int my;
    if (blockIdx.y < 32)      { A = g_P;  M = 4096; vofs = 0;   obase = out;           my = blockIdx.y; }
    else if (blockIdx.y < 40) { A = g_P1; M = 1024; vofs = 192; obase = out + 3145728; my = blockIdx.y - 32; }
    else                      { A = g_P2; M = 256;  vofs = 384; obase = out + 3932160; my = blockIdx.y - 40; }

    const int b  = blockIdx.z;
    const int m0 = my * 128;
    const int n0 = blockIdx.x * 64;          // output channel base
    const float* Ab = A + (size_t)b * M * 4096;
    const float* Vb = g_V + (size_t)b * 4096 * 576 + vofs;
    float* Ob = obase + (size_t)b * 192 * M;

    const int tid = threadIdx.x;
    const int tx  = tid & 15, ty = tid >> 4;
    const int am  = tid >> 2;            // 0..63
    const int ak  = (tid & 3) << 2;      // 0,4,8,12
    const int br2 = tid >> 4;            // 0..15
    const int bc2 = (tid & 15) << 2;     // 0..60

    unsigned long long acc[4][4];
#pragma unroll
    for (int i = 0; i < 4; i++)
#pragma unroll
        for (int j = 0; j < 4; j++) acc[i][j] = 0ull;

#pragma unroll 1
    for (int k0 = 0; k0 < 4096; k0 += 16) {
        float4 a0 = *(const float4*)&Ab[(size_t)(m0 + am) * 4096 + k0 + ak];
        float4 a1 = *(const float4*)&Ab[(size_t)(m0 + am + 64) * 4096 + k0 + ak];
        As[(ak + 0) * 132 + am] = a0.x;
        As[(ak + 1) * 132 + am] = a0.y;
        As[(ak + 2) * 132 + am] = a0.z;
        As[(ak + 3) * 132 + am] = a0.w;
        As[(ak + 0) * 132 + am + 64] = a1.x;
        As[(ak + 1) * 132 + am + 64] = a1.y;
        As[(ak + 2) * 132 + am + 64] = a1.z;
        As[(ak + 3) * 132 + am + 64] = a1.w;
        *(float4*)&Bs[br2][bc2] = *(const float4*)&Vb[(size_t)(k0 + br2) * 576 + n0 + bc2];
        __syncthreads();
#pragma unroll
        for (int c = 0; c < 16; c++) {
            ulonglong2 A0 = *(const ulonglong2*)&As[c * 132 + (ty << 2)];
            ulonglong2 A1 = *(const ulonglong2*)&As[c * 132 + 64 + (ty << 2)];
            float4 bv = *(const float4*)&Bs[c][tx << 2];
            unsigned long long ap[4] = {A0.x, A0.y, A1.x, A1.y};
            unsigned long long bd[4] = {dup2(bv.x), dup2(bv.y), dup2(bv.z), dup2(bv.w)};
#pragma unroll
            for (int i = 0; i < 4; i++)
#pragma unroll
                for (int j = 0; j < 4; j++)
                    fma2(acc[i][j], ap[i], bd[j]);
        }
        __syncthreads();
    }

#pragma unroll
    for (int j = 0; j < 4; j++) {
        const int oc = n0 + (tx << 2) + j;
        const size_t base = (size_t)oc * M + m0 + (ty << 2);
        *(float4*)&Ob[base]      = pair4(acc[0][j], acc[1][j]);
        *(float4*)&Ob[base + 64] = pair4(acc[2][j], acc[3][j]);
    }
}

// ---------------------------------------------------------------------------
extern "C" void kernel_launch(void* const* d_in, const int* in_sizes, int n_in,
                              void* d_out, int out_size)
{
    (void)in_sizes; (void)n_in; (void)out_size;
    const float* fd1 = (const float*)d_in[0];
    const float* fd2 = (const float*)d_in[1];
    const float* ref = (const float*)d_in[2];
    const float* o1  = (const float*)d_in[3];
    const float* o2  = (const float*)d_in[4];
    const float* tw1 = (const float*)d_in[5];
    const float* tb1 = (const float*)d_in[6];
    const float* tw2 = (const float*)d_in[7];
    const float* tb2 = (const float*)d_in[8];
    const float* pw1 = (const float*)d_in[9];
    const float* pb1 = (const float*)d_in[10];
    const float* pw2 = (const float*)d_in[11];
    const float* pb2 = (const float*)d_in[12];
    float* out = (float*)d_out;

    float *t, *f1, *f2;
    cudaGetSymbolAddress((void**)&t,  g_t);
    cudaGetSymbolAddress((void**)&f1, g_f1);
    cudaGetSymbolAddress((void**)&f2, g_f2);
    float* t0 = t;
    float* t1 = t + 3145728;

    // weight slots: 0=theta1, 1=theta2, 2=phi1, 3=phi2
    repack_w<<<5184, 256>>>(tw1, tw2, pw1, pw2);

    // layer 1: both branches in one launch
    conv_gemm<<<dim3(3, 32, 8), 256>>>(fd1, fd2, nullptr, nullptr, 0, 2, tb1, pb1, t0, t1);
    // layer 2: both branches, with residual
    conv_gemm<<<dim3(3, 32, 8), 256>>>(t0, t1, fd1, fd2, 1, 3, tb2, pb2, f1, f2);

    gemm_corr<<<dim3(32, 32, 4), 256>>>(f1, f2);
    softmax_rows<<<16384, 256>>>();
    pool_P1<<<16384, 256>>>();
    pool_P2<<<4096, 256>>>();
    build_V<<<36864, 256>>>(ref, o1, o2);
    gemm_pv<<<dim3(3, 42, 4), 256>>>(out);
}

// round 6
// speedup vs baseline: 1.9712x; 1.0862x over previous
#include <cuda_runtime.h>
#include <cuda_bf16.h>
#include <cstdint>

#define LEAK 0.01f

// ---------------- scratch (device globals; no allocation allowed) ----------
static __device__ float g_wt[1327104];              // repacked weights 4x[1728][192]
static __device__ float g_t [6291456];              // layer1 out, 2 branches
static __device__ float g_f1[3145728];              // theta branch out [4][192][4096]
static __device__ float g_f2[3145728];              // phi branch out
static __device__ float g_P [67108864];             // corr        [4][4096][4096]
static __device__ float g_P1[16777216];             // q-pooled    [4][1024][4096]
static __device__ float g_P2[4194304];              // q-pooled^2  [4][256][4096]
static __device__ float g_V [9437184];              // fused V     [4][4096][576]
// packed bf16 hi/lo operands, layout [b][kc][m][16]  (kc = k/16)
static __device__ __nv_bfloat16 g_ah[3145728];
static __device__ __nv_bfloat16 g_al[3145728];
static __device__ __nv_bfloat16 g_bh[3145728];
static __device__ __nv_bfloat16 g_bl[3145728];

// ---------------- f32x2 packed helpers -------------------------------------
__device__ __forceinline__ void fma2(unsigned long long& d,
                                     unsigned long long a, unsigned long long b)
{
    asm("fma.rn.f32x2 %0, %1, %2, %0;" : "+l"(d) : "l"(a), "l"(b));
}
__device__ __forceinline__ unsigned long long dup2(float x)
{
    unsigned long long d;
    asm("mov.b64 %0, {%1, %2};" : "=l"(d) : "f"(x), "f"(x));
    return d;
}
__device__ __forceinline__ float2 unpk(unsigned long long v)
{
    float2 f;
    asm("mov.b64 {%0, %1}, %2;" : "=f"(f.x), "=f"(f.y) : "l"(v));
    return f;
}
__device__ __forceinline__ float4 pair4(unsigned long long a, unsigned long long b)
{
    float2 x = unpk(a), y = unpk(b);
    return make_float4(x.x, x.y, y.x, y.y);
}

// ---------------- mma.sync helpers (sm_80+ path, works on plain sm_100) ----
__device__ __forceinline__ uint32_t smem_u32(const void* p)
{
    uint32_t a;
    asm("{ .reg .u64 t; cvta.to.shared.u64 t, %1; cvt.u32.u64 %0, t; }" : "=r"(a) : "l"(p));
    return a;
}
__device__ __forceinline__ void ldm4(uint32_t* r, uint32_t addr)
{
    asm volatile("ldmatrix.sync.aligned.m8n8.x4.shared.b16 {%0,%1,%2,%3}, [%4];"
        : "=r"(r[0]), "=r"(r[1]), "=r"(r[2]), "=r"(r[3]) : "r"(addr));
}
__device__ __forceinline__ void mma16816(float* c, const uint32_t* a, const uint32_t* b)
{
    asm volatile("mma.sync.aligned.m16n8k16.row.col.f32.bf16.bf16.f32 "
        "{%0,%1,%2,%3}, {%4,%5,%6,%7}, {%8,%9}, {%0,%1,%2,%3};"
        : "+f"(c[0]), "+f"(c[1]), "+f"(c[2]), "+f"(c[3])
        : "r"(a[0]), "r"(a[1]), "r"(a[2]), "r"(a[3]), "r"(b[0]), "r"(b[1]));
}

// ---------------- weight repack --------------------------------------------
__global__ void repack_w(const float* __restrict__ w0, const float* __restrict__ w1,
                         const float* __restrict__ w2, const float* __restrict__ w3)
{
    int idx = blockIdx.x * 256 + threadIdx.x;           // < 1327104 exact
    int s   = idx / 331776;
    int r   = idx % 331776;
    int k   = r / 192;
    int oc  = r % 192;
    int tap = k / 192;
    int ic  = k % 192;
    const float* w = (s == 0) ? w0 : (s == 1) ? w1 : (s == 2) ? w2 : w3;
    g_wt[idx] = w[(oc * 192 + ic) * 9 + tap];
}

// ---------------- conv3x3 as implicit GEMM ---------------------------------
__global__ void __launch_bounds__(256, 2)
conv_gemm(const float* __restrict__ x0, const float* __restrict__ x1,
          const float* __restrict__ res0, const float* __restrict__ res1,
          int wslot0, int wslot1,
          const float* __restrict__ bias0, const float* __restrict__ bias1,
          float* __restrict__ y0, float* __restrict__ y1)
{
    __shared__ float As[16][128];
    __shared__ float Bs[16][64];

    const int b  = blockIdx.z & 3;
    const int br = blockIdx.z >> 2;
    const float* xb   = (br ? x1 : x0) + (size_t)b * 192 * 4096;
    const float* wt   = g_wt + (size_t)(br ? wslot1 : wslot0) * 331776;
    const float* bias = br ? bias1 : bias0;
    const float* resb = br ? res1 : res0;
    if (resb) resb += (size_t)b * 192 * 4096;
    float* yb = (br ? y1 : y0) + (size_t)b * 192 * 4096;

    const int m0 = blockIdx.y * 128;
    const int n0 = blockIdx.x * 64;
    const int tid = threadIdx.x;
    const int tx = tid & 15, ty = tid >> 4;

    const int lp  = tid & 127;
    const int kk0 = (tid >> 7) * 8;
    const int gp  = m0 + lp;
    const int lh  = gp >> 6, lw = gp & 63;
    const int br2 = tid >> 4;
    const int bc2 = (tid & 15) << 2;

    unsigned long long acc[4][4];
#pragma unroll
    for (int i = 0; i < 4; i++)
#pragma unroll
        for (int j = 0; j < 4; j++) acc[i][j] = 0ull;

#pragma unroll 1
    for (int tap = 0; tap < 9; tap++) {
        const int ky = tap / 3, kx = tap % 3;
        const int off = (ky - 1) * 64 + (kx - 1);
        const bool ok = (lh + ky - 1 >= 0) && (lh + ky - 1 < 64) &&
                        (lw + kx - 1 >= 0) && (lw + kx - 1 < 64);
        const float* srcA = xb + gp + off + (size_t)kk0 * 4096;
        const float* srcB = wt + (size_t)(tap * 192 + br2) * 192 + n0 + bc2;

#pragma unroll 1
        for (int ic0 = 0; ic0 < 192; ic0 += 16) {
#pragma unroll
            for (int kk = 0; kk < 8; kk++)
                As[kk0 + kk][lp] = ok ? __ldg(srcA + (size_t)(ic0 + kk) * 4096) : 0.f;
            *(float4*)&Bs[br2][bc2] = *(const float4*)(srcB + (size_t)ic0 * 192);
            __syncthreads();
#pragma unroll
            for (int c = 0; c < 16; c++) {
                ulonglong2 A0 = *(const ulonglong2*)&As[c][ty << 2];
                ulonglong2 A1 = *(const ulonglong2*)&As[c][64 + (ty << 2)];
                float4 bv = *(const float4*)&Bs[c][tx << 2];
                unsigned long long ap[4] = {A0.x, A0.y, A1.x, A1.y};
                unsigned long long bd[4] = {dup2(bv.x), dup2(bv.y), dup2(bv.z), dup2(bv.w)};
#pragma unroll
                for (int i = 0; i < 4; i++)
#pragma unroll
                    for (int j = 0; j < 4; j++)
                        fma2(acc[i][j], ap[i], bd[j]);
            }
            __syncthreads();
        }
    }

#pragma unroll
    for (int j = 0; j < 4; j++) {
        const int oc = n0 + (tx << 2) + j;
        const float bv = bias[oc];
        const size_t base = (size_t)oc * 4096 + m0 + (ty << 2);
        float4 v0 = pair4(acc[0][j], acc[1][j]);
        float4 v1 = pair4(acc[2][j], acc[3][j]);
        v0.x += bv; v0.y += bv; v0.z += bv; v0.w += bv;
        v1.x += bv; v1.y += bv; v1.z += bv; v1.w += bv;
        v0.x = v0.x > 0.f ? v0.x : LEAK * v0.x;
        v0.y = v0.y > 0.f ? v0.y : LEAK * v0.y;
        v0.z = v0.z > 0.f ? v0.z : LEAK * v0.z;
        v0.w = v0.w > 0.f ? v0.w : LEAK * v0.w;
        v1.x = v1.x > 0.f ? v1.x : LEAK * v1.x;
        v1.y = v1.y > 0.f ? v1.y : LEAK * v1.y;
        v1.z = v1.z > 0.f ? v1.z : LEAK * v1.z;
        v1.w = v1.w > 0.f ? v1.w : LEAK * v1.w;
        if (resb) {
            float4 r0 = *(const float4*)&resb[base];
            float4 r1 = *(const float4*)&resb[base + 64];
            v0.x += r0.x; v0.y += r0.y; v0.z += r0.z; v0.w += r0.w;
            v1.x += r1.x; v1.y += r1.y; v1.z += r1.z; v1.w += r1.w;
        }
        *(float4*)&yb[base]      = v0;
        *(float4*)&yb[base + 64] = v1;
    }
}

// ---------------- pack f1/f2 -> transposed k-chunked bf16 hi/lo ------------
// out[b][kc][m][16]:  grid (32 mblk, 12 kc, 8 = b*2+src), 256 threads
__global__ void pack_bf16(const float* __restrict__ f1, const float* __restrict__ f2)
{
    __shared__ __nv_bfloat16 sh[2048], sl[2048];   // [m][16]
    const int mb = blockIdx.x, kc = blockIdx.y;
    const int b = blockIdx.z >> 1, src = blockIdx.z & 1;
    const float* f = (src ? f2 : f1) + (size_t)b * 192 * 4096;
    __nv_bfloat16* oh = src ? g_bh : g_ah;
    __nv_bfloat16* ol = src ? g_bl : g_al;
    const int tid = threadIdx.x;
    const int m  = tid & 127;
    const int k0 = tid >> 7;                       // 0..1
    const int m0 = mb * 128;
#pragma unroll
    for (int kk = 0; kk < 16; kk += 2) {
        int k = kk + k0;
        float x = f[(size_t)(kc * 16 + k) * 4096 + m0 + m];
        __nv_bfloat16 h = __float2bfloat16(x);
        __nv_bfloat16 l = __float2bfloat16(x - __bfloat162float(h));
        sh[m * 16 + k] = h;
        sl[m * 16 + k] = l;
    }
    __syncthreads();
    const size_t ob = ((size_t)(b * 12 + kc) * 4096 + m0) * 16;
    ((uint4*)(oh + ob))[tid] = ((const uint4*)sh)[tid];
    ((uint4*)(ol + ob))[tid] = ((const uint4*)sl)[tid];
}

// ---------------- S = f1^T f2 via mma.sync bf16 split ----------------------
// CTA tile 128m x 64n, 128 threads (4 warps 2x2), warp tile 64x32.
// K=192 as 12 chunks of 16; per chunk 3 split-products (hh, hl, lh).
// grid (64 nblk, 32 mblk, 4 batch).
__global__ void __launch_bounds__(128)
gemm_corr_mma()
{
    // 48B row stride -> conflict-free ldmatrix (8 rows hit 8 distinct 16B groups)
    __shared__ __nv_bfloat16 sA[2][2][128 * 24];
    __shared__ __nv_bfloat16 sB[2][2][64 * 24];

    const int b  = blockIdx.z;
    const int m0 = blockIdx.y * 128;
    const int n0 = blockIdx.x * 64;
    float* Pb = g_P + (size_t)b * 4096 * 4096;

    const int tid = threadIdx.x;
    const int wid = tid >> 5, lid = tid & 31;
    const int wm = wid & 1, wn = wid >> 1;

    float c[4][4][4];
#pragma unroll
    for (int i = 0; i < 4; i++)
#pragma unroll
        for (int j = 0; j < 4; j++)
#pragma unroll
            for (int k = 0; k < 4; k++) c[i][j][k] = 0.f;

    // -------- chunk 0 load --------
    {
        const size_t oa = ((size_t)(b * 12 + 0) * 4096 + m0) * 16;
        const size_t ob = ((size_t)(b * 12 + 0) * 4096 + n0) * 16;
#pragma unroll
        for (int i = 0; i < 2; i++) {
            int idx = i * 128 + tid;
            int m = idx >> 1, half = idx & 1;
            *(uint4*)&sA[0][0][m * 24 + half * 8] = ((const uint4*)(g_ah + oa))[idx];
            *(uint4*)&sA[0][1][m * 24 + half * 8] = ((const uint4*)(g_al + oa))[idx];
        }
        {
            int n = tid >> 1, half = tid & 1;
            *(uint4*)&sB[0][0][n * 24 + half * 8] = ((const uint4*)(g_bh + ob))[tid];
            *(uint4*)&sB[0][1][n * 24 + half * 8] = ((const uint4*)(g_bl + ob))[tid];
        }
    }
    __syncthreads();

#pragma unroll 1
    for (int kc = 0; kc < 12; kc++) {
        const int buf = kc & 1;
        if (kc < 11) {
            const int nb = buf ^ 1;
            const size_t oa = ((size_t)(b * 12 + kc + 1) * 4096 + m0) * 16;
            const size_t ob = ((size_t)(b * 12 + kc + 1) * 4096 + n0) * 16;
#pragma unroll
            for (int i = 0; i < 2; i++) {
                int idx = i * 128 + tid;
                int m = idx >> 1, half = idx & 1;
                *(uint4*)&sA[nb][0][m * 24 + half * 8] = ((const uint4*)(g_ah + oa))[idx];
                *(uint4*)&sA[nb][1][m * 24 + half * 8] = ((const uint4*)(g_al + oa))[idx];
            }
            {
                int n = tid >> 1, half = tid & 1;
                *(uint4*)&sB[nb][0][n * 24 + half * 8] = ((const uint4*)(g_bh + ob))[tid];
                *(uint4*)&sB[nb][1][n * 24 + half * 8] = ((const uint4*)(g_bl + ob))[tid];
            }
        }

        uint32_t Ah[4][4], Al[4][4], Bh[4][2], Bl[4][2];
        const int arow = (lid & 7) + ((lid >> 3) & 1) * 8;
        const int acol = ((lid >> 4) & 1) * 16;
#pragma unroll
        for (int mf = 0; mf < 4; mf++) {
            const int row = wm * 64 + mf * 16 + arow;
            ldm4(Ah[mf], smem_u32(&sA[buf][0][row * 24]) + acol);
            ldm4(Al[mf], smem_u32(&sA[buf][1][row * 24]) + acol);
        }
        const int brow = (lid & 7) + ((lid >> 4) & 1) * 8;
        const int bcol = ((lid >> 3) & 1) * 16;
#pragma unroll
        for (int nf2 = 0; nf2 < 2; nf2++) {
            const int row = wn * 32 + nf2 * 16 + brow;
            uint32_t r[4];
            ldm4(r, smem_u32(&sB[buf][0][row * 24]) + bcol);
            Bh[nf2 * 2][0] = r[0]; Bh[nf2 * 2][1] = r[1];
            Bh[nf2 * 2 + 1][0] = r[2]; Bh[nf2 * 2 + 1][1] = r[3];
            ldm4(r, smem_u32(&sB[buf][1][row * 24]) + bcol);
            Bl[nf2 * 2][0] = r[0]; Bl[nf2 * 2][1] = r[1];
            Bl[nf2 * 2 + 1][0] = r[2]; Bl[nf2 * 2 + 1][1] = r[3];
        }

#pragma unroll
        for (int mf = 0; mf < 4; mf++)
#pragma unroll
            for (int nf = 0; nf < 4; nf++) {
                mma16816(c[mf][nf], Ah[mf], Bh[nf]);
                mma16816(c[mf][nf], Ah[mf], Bl[nf]);
                mma16816(c[mf][nf], Al[mf], Bh[nf]);
            }
        __syncthreads();
    }

    // -------- epilogue: direct stores (32B full sectors per quad) ----------
    const int g = lid >> 2;
    const int colq = (lid & 3) * 2;
#pragma unroll
    for (int mf = 0; mf < 4; mf++) {
        const int q = m0 + wm * 64 + mf * 16 + g;
#pragma unroll
        for (int nf = 0; nf < 4; nf++) {
            const int col = n0 + wn * 32 + nf * 8 + colq;
            *(float2*)&Pb[(size_t)q * 4096 + col]       = make_float2(c[mf][nf][0], c[mf][nf][1]);
            *(float2*)&Pb[(size_t)(q + 8) * 4096 + col] = make_float2(c[mf][nf][2], c[mf][nf][3]);
        }
    }
}

// ---------------- row softmax over 4096 keys -------------------------------
__global__ void softmax_rows()
{
    __shared__ float s[4096];
    __shared__ float red[256];
    float* p = g_P + (size_t)blockIdx.x * 4096;
    const int tid = threadIdx.x;

    float m = -1e30f;
    for (int i = tid; i < 4096; i += 256) { float v = p[i]; s[i] = v; m = fmaxf(m, v); }
    red[tid] = m; __syncthreads();
    for (int o = 128; o > 0; o >>= 1) {
        if (tid < o) red[tid] = fmaxf(red[tid], red[tid + o]);
        __syncthreads();
    }
    m = red[0];
    __syncthreads();

    float sum = 0.f;
    for (int i = tid; i < 4096; i += 256) { float e = __expf(s[i] - m); s[i] = e; sum += e; }
    red[tid] = sum; __syncthreads();
    for (int o = 128; o > 0; o >>= 1) {
        if (tid < o) red[tid] += red[tid + o];
        __syncthreads();
    }
    const float inv = 1.0f / red[0];
    for (int i = tid; i < 4096; i += 256) p[i] = s[i] * inv;
}

// ---------------- query-grid pooling of P ----------------------------------
__global__ void pool_P1()
{
    const int idx = blockIdx.x * 256 + threadIdx.x;
    const int b  = idx >> 20;
    const int q1 = (idx >> 10) & 1023;
    const int k4 = idx & 1023;
    const int h2 = q1 >> 5, w2 = q1 & 31;
    const int r  = (h2 * 2) * 64 + w2 * 2;
    const float4* base = (const float4*)(g_P + ((size_t)b * 4096 + r) * 4096) + k4;
    float4 a = base[0], c = base[1024], d = base[64 * 1024], e = base[65 * 1024];
    float4 o;
    o.x = 0.25f * (a.x + c.x + d.x + e.x);
    o.y = 0.25f * (a.y + c.y + d.y + e.y);
    o.z = 0.25f * (a.z + c.z + d.z + e.z);
    o.w = 0.25f * (a.w + c.w + d.w + e.w);
    ((float4*)(g_P1 + ((size_t)b * 1024 + q1) * 4096))[k4] = o;
}

__global__ void pool_P2()
{
    const int idx = blockIdx.x * 256 + threadIdx.x;
    const int b  = idx >> 18;
    const int q2 = (idx >> 10) & 255;
    const int k4 = idx & 1023;
    const int h4 = q2 >> 4, w4 = q2 & 15;
    const int r  = (h4 * 2) * 32 + w4 * 2;
    const float4* base = (const float4*)(g_P1 + ((size_t)b * 1024 + r) * 4096) + k4;
    float4 a = base[0], c = base[1024], d = base[32 * 1024], e = base[33 * 1024];
    float4 o;
    o.x = 0.25f * (a.x + c.x + d.x + e.x);
    o.y = 0.25f * (a.y + c.y + d.y + e.y);
    o.z = 0.25f * (a.z + c.z + d.z + e.z);
    o.w = 0.25f * (a.w + c.w + d.w + e.w);
    ((float4*)(g_P2 + ((size_t)b * 256 + q2) * 4096))[k4] = o;
}

// ---------------- fused value matrix V[b][k][576] --------------------------
__global__ void build_V(const float* __restrict__ ref,
                        const float* __restrict__ o1,
                        const float* __restrict__ o2)
{
    const int idx = blockIdx.x * 256 + threadIdx.x;
    const int v = idx % 576;
    const int k = (idx / 576) & 4095;
    const int b = idx / (576 * 4096);
    const int h = k >> 6, w = k & 63;
    float val;
    if (v < 192)
        val = ref[(((size_t)b * 192 + v) << 12) + k];
    else if (v < 384)
        val = 0.25f   * o1[(((size_t)b * 192 + (v - 192)) << 10) + ((h >> 1) << 5) + (w >> 1)];
    else
        val = 0.0625f * o2[(((size_t)b * 192 + (v - 384)) << 8)  + ((h >> 2) << 4) + (w >> 2)];
    g_V[idx] = val;
}

// ---------------- combined PV GEMM -> final outputs ------------------------
__global__ void __launch_bounds__(256, 2)
gemm_pv(float* __restrict__ out)
{
    __shared__ float As[16 * 132];
    __shared__ float Bs[16][64];

    const float* A; int M; int vofs; float* obase; int my;
    if (blockIdx.y < 32)      { A = g_P;  M = 4096; vofs = 0;   obase = out;           my = blockIdx.y; }
    else if (blockIdx.y < 40) { A = g_P1; M = 1024; vofs = 192; obase = out + 3145728; my = blockIdx.y - 32; }
    else                      { A = g_P2; M = 256;  vofs = 384; obase = out + 3932160; my = blockIdx.y - 40; }

    const int b  = blockIdx.z;
    const int m0 = my * 128;
    const int n0 = blockIdx.x * 64;
    const float* Ab = A + (size_t)b * M * 4096;
    const float* Vb = g_V + (size_t)b * 4096 * 576 + vofs;
    float* Ob = obase + (size_t)b * 192 * M;

    const int tid = threadIdx.x;
    const int tx  = tid & 15, ty = tid >> 4;
    const int am  = tid >> 2;
    const int ak  = (tid & 3) << 2;
    const int br2 = tid >> 4;
    const int bc2 = (tid & 15) << 2;

    unsigned long long acc[4][4];
#pragma unroll
    for (int i = 0; i < 4; i++)
#pragma unroll
        for (int j = 0; j < 4; j++) acc[i][j] = 0ull;

#pragma unroll 1
    for (int k0 = 0; k0 < 4096; k0 += 16) {
        float4 a0 = *(const float4*)&Ab[(size_t)(m0 + am) * 4096 + k0 + ak];
        float4 a1 = *(const float4*)&Ab[(size_t)(m0 + am + 64) * 4096 + k0 + ak];
        As[(ak + 0) * 132 + am] = a0.x;
        As[(ak + 1) * 132 + am] = a0.y;
        As[(ak + 2) * 132 + am] = a0.z;
        As[(ak + 3) * 132 + am] = a0.w;
        As[(ak + 0) * 132 + am + 64] = a1.x;
        As[(ak + 1) * 132 + am + 64] = a1.y;
        As[(ak + 2) * 132 + am + 64] = a1.z;
        As[(ak + 3) * 132 + am + 64] = a1.w;
        *(float4*)&Bs[br2][bc2] = *(const float4*)&Vb[(size_t)(k0 + br2) * 576 + n0 + bc2];
        __syncthreads();
#pragma unroll
        for (int c = 0; c < 16; c++) {
            ulonglong2 A0 = *(const ulonglong2*)&As[c * 132 + (ty << 2)];
            ulonglong2 A1 = *(const ulonglong2*)&As[c * 132 + 64 + (ty << 2)];
            float4 bv = *(const float4*)&Bs[c][tx << 2];
            unsigned long long ap[4] = {A0.x, A0.y, A1.x, A1.y};
            unsigned long long bd[4] = {dup2(bv.x), dup2(bv.y), dup2(bv.z), dup2(bv.w)};
#pragma unroll
            for (int i = 0; i < 4; i++)
#pragma unroll
                for (int j = 0; j < 4; j++)
                    fma2(acc[i][j], ap[i], bd[j]);
        }
        __syncthreads();
    }

#pragma unroll
    for (int j = 0; j < 4; j++) {
        const int oc = n0 + (tx << 2) + j;
        const size_t base = (size_t)oc * M + m0 + (ty << 2);
        *(float4*)&Ob[base]      = pair4(acc[0][j], acc[1][j]);
        *(float4*)&Ob[base + 64] = pair4(acc[2][j], acc[3][j]);
    }
}

// ---------------------------------------------------------------------------
extern "C" void kernel_launch(void* const* d_in, const int* in_sizes, int n_in,
                              void* d_out, int out_size)
{
    (void)in_sizes; (void)n_in; (void)out_size;
    const float* fd1 = (const float*)d_in[0];
    const float* fd2 = (const float*)d_in[1];
    const float* ref = (const float*)d_in[2];
    const float* o1  = (const float*)d_in[3];
    const float* o2  = (const float*)d_in[4];
    const float* tw1 = (const float*)d_in[5];
    const float* tb1 = (const float*)d_in[6];
    const float* tw2 = (const float*)d_in[7];
    const float* tb2 = (const float*)d_in[8];
    const float* pw1 = (const float*)d_in[9];
    const float* pb1 = (const float*)d_in[10];
    const float* pw2 = (const float*)d_in[11];
    const float* pb2 = (const float*)d_in[12];
    float* out = (float*)d_out;

    float *t, *f1, *f2;
    cudaGetSymbolAddress((void**)&t,  g_t);
    cudaGetSymbolAddress((void**)&f1, g_f1);
    cudaGetSymbolAddress((void**)&f2, g_f2);
    float* t0 = t;
    float* t1 = t + 3145728;

    repack_w<<<5184, 256>>>(tw1, tw2, pw1, pw2);

    conv_gemm<<<dim3(3, 32, 8), 256>>>(fd1, fd2, nullptr, nullptr, 0, 2, tb1, pb1, t0, t1);
    conv_gemm<<<dim3(3, 32, 8), 256>>>(t0, t1, fd1, fd2, 1, 3, tb2, pb2, f1, f2);

    pack_bf16<<<dim3(32, 12, 8), 256>>>(f1, f2);
    gemm_corr_mma<<<dim3(64, 32, 4), 128>>>();
    softmax_rows<<<16384, 256>>>();
    pool_P1<<<16384, 256>>>();
    pool_P2<<<4096, 256>>>();
    build_V<<<36864, 256>>>(ref, o1, o2);
    gemm_pv<<<dim3(3, 42, 4), 256>>>(out);
}

// round 8
// speedup vs baseline: 2.2677x; 1.1504x over previous
#include <cuda_runtime.h>
#include <cuda_bf16.h>
#include <cstdint>

#define LEAK 0.01f

// ---------------- scratch (device globals; no allocation allowed) ----------
static __device__ float g_wt[1327104];              // repacked weights
static __device__ float g_t [6291456];              // layer1 out, 2 branches
static __device__ float g_f1[3145728];              // theta out [4][192][4096]
static __device__ float g_f2[3145728];              // phi out
static __device__ float g_P [67108864];             // corr logits [4][4096][4096]
// bf16 hi/lo pairs
static __device__ __nv_bfloat16 g_Ph [67108864];    // softmax(P) hi
static __device__ __nv_bfloat16 g_Pl [67108864];    // softmax(P) lo
static __device__ __nv_bfloat16 g_P1h[16777216];    // pooled [4][1024][4096]
static __device__ __nv_bfloat16 g_P1l[16777216];
static __device__ __nv_bfloat16 g_P2h[4194304];     // pooled^2 [4][256][4096]
static __device__ __nv_bfloat16 g_P2l[4194304];
static __device__ __nv_bfloat16 g_Vth[9437184];     // V^T [4][576][4096]
static __device__ __nv_bfloat16 g_Vtl[9437184];
// packed bf16 operands for corr, layout [b][kc][m][16]
static __device__ __nv_bfloat16 g_ah[3145728];
static __device__ __nv_bfloat16 g_al[3145728];
static __device__ __nv_bfloat16 g_bh[3145728];
static __device__ __nv_bfloat16 g_bl[3145728];

// ---------------- f32x2 packed helpers -------------------------------------
__device__ __forceinline__ void fma2(unsigned long long& d,
                                     unsigned long long a, unsigned long long b)
{
    asm("fma.rn.f32x2 %0, %1, %2, %0;" : "+l"(d) : "l"(a), "l"(b));
}
__device__ __forceinline__ unsigned long long dup2(float x)
{
    unsigned long long d;
    asm("mov.b64 %0, {%1, %2};" : "=l"(d) : "f"(x), "f"(x));
    return d;
}
__device__ __forceinline__ float2 unpk(unsigned long long v)
{
    float2 f;
    asm("mov.b64 {%0, %1}, %2;" : "=f"(f.x), "=f"(f.y) : "l"(v));
    return f;
}
__device__ __forceinline__ float4 pair4(unsigned long long a, unsigned long long b)
{
    float2 x = unpk(a), y = unpk(b);
    return make_float4(x.x, x.y, y.x, y.y);
}

// ---------------- bf16 split helpers ---------------------------------------
__device__ __forceinline__ void split2(float v0, float v1, uint32_t& h, uint32_t& l)
{
    __nv_bfloat16 h0 = __float2bfloat16(v0), h1 = __float2bfloat16(v1);
    __nv_bfloat162 hp = __halves2bfloat162(h0, h1);
    __nv_bfloat162 lp = __halves2bfloat162(
        __float2bfloat16(v0 - __bfloat162float(h0)),
        __float2bfloat16(v1 - __bfloat162float(h1)));
    h = *(uint32_t*)&hp;
    l = *(uint32_t*)&lp;
}
__device__ __forceinline__ float2 rec2(uint32_t h, uint32_t l)
{
    float2 a = __bfloat1622float2(*(__nv_bfloat162*)&h);
    float2 b = __bfloat1622float2(*(__nv_bfloat162*)&l);
    return make_float2(a.x + b.x, a.y + b.y);
}

// ---------------- mma.sync helpers ------------------------------------------
__device__ __forceinline__ uint32_t smem_u32(const void* p)
{
    uint32_t a;
    asm("{ .reg .u64 t; cvta.to.shared.u64 t, %1; cvt.u32.u64 %0, t; }" : "=r"(a) : "l"(p));
    return a;
}
__device__ __forceinline__ void ldm4(uint32_t* r, uint32_t addr)
{
    asm volatile("ldmatrix.sync.aligned.m8n8.x4.shared.b16 {%0,%1,%2,%3}, [%4];"
        : "=r"(r[0]), "=r"(r[1]), "=r"(r[2]), "=r"(r[3]) : "r"(addr));
}
__device__ __forceinline__ void mma16816(float* c, const uint32_t* a, const uint32_t* b)
{
    asm volatile("mma.sync.aligned.m16n8k16.row.col.f32.bf16.bf16.f32 "
        "{%0,%1,%2,%3}, {%4,%5,%6,%7}, {%8,%9}, {%0,%1,%2,%3};"
        : "+f"(c[0]), "+f"(c[1]), "+f"(c[2]), "+f"(c[3])
        : "r"(a[0]), "r"(a[1]), "r"(a[2]), "r"(a[3]), "r"(b[0]), "r"(b[1]));
}

// ---------------- weight repack --------------------------------------------
__global__ void repack_w(const float* __restrict__ w0, const float* __restrict__ w1,
                         const float* __restrict__ w2, const float* __restrict__ w3)
{
    int idx = blockIdx.x * 256 + threadIdx.x;           // < 1327104 exact
    int s   = idx / 331776;
    int r   = idx % 331776;
    int k   = r / 192;
    int oc  = r % 192;
    int tap = k / 192;
    int ic  = k % 192;
    const float* w = (s == 0) ? w0 : (s == 1) ? w1 : (s == 2) ? w2 : w3;
    g_wt[idx] = w[(oc * 192 + ic) * 9 + tap];
}

// ---------------- conv3x3 as implicit GEMM ---------------------------------
__global__ void __launch_bounds__(256, 2)
conv_gemm(const float* __restrict__ x0, const float* __restrict__ x1,
          const float* __restrict__ res0, const float* __restrict__ res1,
          int wslot0, int wslot1,
          const float* __restrict__ bias0, const float* __restrict__ bias1,
          float* __restrict__ y0, float* __restrict__ y1)
{
    __shared__ float As[16][128];
    __shared__ float Bs[16][64];

    const int b  = blockIdx.z & 3;
    const int br = blockIdx.z >> 2;
    const float* xb   = (br ? x1 : x0) + (size_t)b * 192 * 4096;
    const float* wt   = g_wt + (size_t)(br ? wslot1 : wslot0) * 331776;
    const float* bias = br ? bias1 : bias0;
    const float* resb = br ? res1 : res0;
    if (resb) resb += (size_t)b * 192 * 4096;
    float* yb = (br ? y1 : y0) + (size_t)b * 192 * 4096;

    const int m0 = blockIdx.y * 128;
    const int n0 = blockIdx.x * 64;
    const int tid = threadIdx.x;
    const int tx = tid & 15, ty = tid >> 4;

    const int lp  = tid & 127;
    const int kk0 = (tid >> 7) * 8;
    const int gp  = m0 + lp;
    const int lh  = gp >> 6, lw = gp & 63;
    const int br2 = tid >> 4;
    const int bc2 = (tid & 15) << 2;

    unsigned long long acc[4][4];
#pragma unroll
    for (int i = 0; i < 4; i++)
#pragma unroll
        for (int j = 0; j < 4; j++) acc[i][j] = 0ull;

#pragma unroll 1
    for (int tap = 0; tap < 9; tap++) {
        const int ky = tap / 3, kx = tap % 3;
        const int off = (ky - 1) * 64 + (kx - 1);
        const bool ok = (lh + ky - 1 >= 0) && (lh + ky - 1 < 64) &&
                        (lw + kx - 1 >= 0) && (lw + kx - 1 < 64);
        const float* srcA = xb + gp + off + (size_t)kk0 * 4096;
        const float* srcB = wt + (size_t)(tap * 192 + br2) * 192 + n0 + bc2;

#pragma unroll 1
        for (int ic0 = 0; ic0 < 192; ic0 += 16) {
#pragma unroll
            for (int kk = 0; kk < 8; kk++)
                As[kk0 + kk][lp] = ok ? __ldg(srcA + (size_t)(ic0 + kk) * 4096) : 0.f;
            *(float4*)&Bs[br2][bc2] = *(const float4*)(srcB + (size_t)ic0 * 192);
            __syncthreads();
#pragma unroll
            for (int c = 0; c < 16; c++) {
                ulonglong2 A0 = *(const ulonglong2*)&As[c][ty << 2];
                ulonglong2 A1 = *(const ulonglong2*)&As[c][64 + (ty << 2)];
                float4 bv = *(const float4*)&Bs[c][tx << 2];
                unsigned long long ap[4] = {A0.x, A0.y, A1.x, A1.y};
                unsigned long long bd[4] = {dup2(bv.x), dup2(bv.y), dup2(bv.z), dup2(bv.w)};
#pragma unroll
                for (int i = 0; i < 4; i++)
#pragma unroll
                    for (int j = 0; j < 4; j++)
                        fma2(acc[i][j], ap[i], bd[j]);
            }
            __syncthreads();
        }
    }

#pragma unroll
    for (int j = 0; j < 4; j++) {
        const int oc = n0 + (tx << 2) + j;
        const float bv = bias[oc];
        const size_t base = (size_t)oc * 4096 + m0 + (ty << 2);
        float4 v0 = pair4(acc[0][j], acc[1][j]);
        float4 v1 = pair4(acc[2][j], acc[3][j]);
        v0.x += bv; v0.y += bv; v0.z += bv; v0.w += bv;
        v1.x += bv; v1.y += bv; v1.z += bv; v1.w += bv;
        v0.x = v0.x > 0.f ? v0.x : LEAK * v0.x;
        v0.y = v0.y > 0.f ? v0.y : LEAK * v0.y;
        v0.z = v0.z > 0.f ? v0.z : LEAK * v0.z;
        v0.w = v0.w > 0.f ? v0.w : LEAK * v0.w;
        v1.x = v1.x > 0.f ? v1.x : LEAK * v1.x;
        v1.y = v1.y > 0.f ? v1.y : LEAK * v1.y;
        v1.z = v1.z > 0.f ? v1.z : LEAK * v1.z;
        v1.w = v1.w > 0.f ? v1.w : LEAK * v1.w;
        if (resb) {
            float4 r0 = *(const float4*)&resb[base];
            float4 r1 = *(const float4*)&resb[base + 64];
            v0.x += r0.x; v0.y += r0.y; v0.z += r0.z; v0.w += r0.w;
            v1.x += r1.x; v1.y += r1.y; v1.z += r1.z; v1.w += r1.w;
        }
        *(float4*)&yb[base]      = v0;
        *(float4*)&yb[base + 64] = v1;
    }
}

// ---------------- pack f1/f2 -> transposed k-chunked bf16 hi/lo ------------
__global__ void pack_bf16(const float* __restrict__ f1, const float* __restrict__ f2)
{
    __shared__ __nv_bfloat16 sh[2048], sl[2048];
    const int mb = blockIdx.x, kc = blockIdx.y;
    const int b = blockIdx.z >> 1, src = blockIdx.z & 1;
    const float* f = (src ? f2 : f1) + (size_t)b * 192 * 4096;
    __nv_bfloat16* oh = src ? g_bh : g_ah;
    __nv_bfloat16* ol = src ? g_bl : g_al;
    const int tid = threadIdx.x;
    const int m  = tid & 127;
    const int k0 = tid >> 7;
    const int m0 = mb * 128;
#pragma unroll
    for (int kk = 0; kk < 16; kk += 2) {
        int k = kk + k0;
        float x = f[(size_t)(kc * 16 + k) * 4096 + m0 + m];
        __nv_bfloat16 h = __float2bfloat16(x);
        __nv_bfloat16 l = __float2bfloat16(x - __bfloat162float(h));
        sh[m * 16 + k] = h;
        sl[m * 16 + k] = l;
    }
    __syncthreads();
    const size_t ob = ((size_t)(b * 12 + kc) * 4096 + m0) * 16;
    ((uint4*)(oh + ob))[tid] = ((const uint4*)sh)[tid];
    ((uint4*)(ol + ob))[tid] = ((const uint4*)sl)[tid];
}

// ---------------- S = f1^T f2 via mma.sync bf16 split ----------------------
__global__ void __launch_bounds__(128)
gemm_corr_mma()
{
    __shared__ __nv_bfloat16 sA[2][2][128 * 24];
    __shared__ __nv_bfloat16 sB[2][2][64 * 24];

    const int b  = blockIdx.z;
    const int m0 = blockIdx.y * 128;
    const int n0 = blockIdx.x * 64;
    float* Pb = g_P + (size_t)b * 4096 * 4096;

    const int tid = threadIdx.x;
    const int wid = tid >> 5, lid = tid & 31;
    const int wm = wid & 1, wn = wid >> 1;

    float c[4][4][4];
#pragma unroll
    for (int i = 0; i < 4; i++)
#pragma unroll
        for (int j = 0; j < 4; j++)
#pragma unroll
            for (int k = 0; k < 4; k++) c[i][j][k] = 0.f;

    {
        const size_t oa = ((size_t)(b * 12 + 0) * 4096 + m0) * 16;
        const size_t ob = ((size_t)(b * 12 + 0) * 4096 + n0) * 16;
#pragma unroll
        for (int i = 0; i < 2; i++) {
            int idx = i * 128 + tid;
            int m = idx >> 1, half = idx & 1;
            *(uint4*)&sA[0][0][m * 24 + half * 8] = ((const uint4*)(g_ah + oa))[idx];
            *(uint4*)&sA[0][1][m * 24 + half * 8] = ((const uint4*)(g_al + oa))[idx];
        }
        {
            int n = tid >> 1, half = tid & 1;
            *(uint4*)&sB[0][0][n * 24 + half * 8] = ((const uint4*)(g_bh + ob))[tid];
            *(uint4*)&sB[0][1][n * 24 + half * 8] = ((const uint4*)(g_bl + ob))[tid];
        }
    }
    __syncthreads();

#pragma unroll 1
    for (int kc = 0; kc < 12; kc++) {
        const int buf = kc & 1;
        if (kc < 11) {
            const int nb = buf ^ 1;
            const size_t oa = ((size_t)(b * 12 + kc + 1) * 4096 + m0) * 16;
            const size_t ob = ((size_t)(b * 12 + kc + 1) * 4096 + n0) * 16;
#pragma unroll
            for (int i = 0; i < 2; i++) {
                int idx = i * 128 + tid;
                int m = idx >> 1, half = idx & 1;
                *(uint4*)&sA[nb][0][m * 24 + half * 8] = ((const uint4*)(g_ah + oa))[idx];
                *(uint4*)&sA[nb][1][m * 24 + half * 8] = ((const uint4*)(g_al + oa))[idx];
            }
            {
                int n = tid >> 1, half = tid & 1;
                *(uint4*)&sB[nb][0][n * 24 + half * 8] = ((const uint4*)(g_bh + ob))[tid];
                *(uint4*)&sB[nb][1][n * 24 + half * 8] = ((const uint4*)(g_bl + ob))[tid];
            }
        }

        uint32_t Ah[4][4], Al[4][4], Bh[4][2], Bl[4][2];
        const int arow = (lid & 7) + ((lid >> 3) & 1) * 8;
        const int acol = ((lid >> 4) & 1) * 16;
#pragma unroll
        for (int mf = 0; mf < 4; mf++) {
            const int row = wm * 64 + mf * 16 + arow;
            ldm4(Ah[mf], smem_u32(&sA[buf][0][row * 24]) + acol);
            ldm4(Al[mf], smem_u32(&sA[buf][1][row * 24]) + acol);
        }
        const int brow = (lid & 7) + ((lid >> 4) & 1) * 8;
        const int bcol = ((lid >> 3) & 1) * 16;
#pragma unroll
        for (int nf2 = 0; nf2 < 2; nf2++) {
            const int row = wn * 32 + nf2 * 16 + brow;
            uint32_t r[4];
            ldm4(r, smem_u32(&sB[buf][0][row * 24]) + bcol);
            Bh[nf2 * 2][0] = r[0]; Bh[nf2 * 2][1] = r[1];
            Bh[nf2 * 2 + 1][0] = r[2]; Bh[nf2 * 2 + 1][1] = r[3];
            ldm4(r, smem_u32(&sB[buf][1][row * 24]) + bcol);
            Bl[nf2 * 2][0] = r[0]; Bl[nf2 * 2][1] = r[1];
            Bl[nf2 * 2 + 1][0] = r[2]; Bl[nf2 * 2 + 1][1] = r[3];
        }

#pragma unroll
        for (int mf = 0; mf < 4; mf++)
#pragma unroll
            for (int nf = 0; nf < 4; nf++) {
                mma16816(c[mf][nf], Ah[mf], Bh[nf]);
                mma16816(c[mf][nf], Ah[mf], Bl[nf]);
                mma16816(c[mf][nf], Al[mf], Bh[nf]);
            }
        __syncthreads();
    }

    const int g = lid >> 2;
    const int colq = (lid & 3) * 2;
#pragma unroll
    for (int mf = 0; mf < 4; mf++) {
        const int q = m0 + wm * 64 + mf * 16 + g;
#pragma unroll
        for (int nf = 0; nf < 4; nf++) {
            const int col = n0 + wn * 32 + nf * 8 + colq;
            *(float2*)&Pb[(size_t)q * 4096 + col]       = make_float2(c[mf][nf][0], c[mf][nf][1]);
            *(float2*)&Pb[(size_t)(q + 8) * 4096 + col] = make_float2(c[mf][nf][2], c[mf][nf][3]);
        }
    }
}

// ---------------- row softmax -> bf16 hi/lo pairs --------------------------
__global__ void softmax_rows_bf()
{
    __shared__ float s[4096];
    __shared__ float red[256];
    const size_t row = blockIdx.x;
    const float* p = g_P + row * 4096;
    const int tid = threadIdx.x;

    float m = -1e30f;
    for (int i = tid; i < 4096; i += 256) { float v = p[i]; s[i] = v; m = fmaxf(m, v); }
    red[tid] = m; __syncthreads();
    for (int o = 128; o > 0; o >>= 1) {
        if (tid < o) red[tid] = fmaxf(red[tid], red[tid + o]);
        __syncthreads();
    }
    m = red[0];
    __syncthreads();

    float sum = 0.f;
    for (int i = tid; i < 4096; i += 256) { float e = __expf(s[i] - m); s[i] = e; sum += e; }
    red[tid] = sum; __syncthreads();
    for (int o = 128; o > 0; o >>= 1) {
        if (tid < o) red[tid] += red[tid + o];
        __syncthreads();
    }
    const float inv = 1.0f / red[0];
    __syncthreads();

    __nv_bfloat16* ph = g_Ph + row * 4096;
    __nv_bfloat16* pl = g_Pl + row * 4096;
#pragma unroll
    for (int pass = 0; pass < 2; pass++) {
        const int g2 = pass * 256 + tid;           // 16B group (8 bf16)
        uint32_t hh[4], ll[4];
#pragma unroll
        for (int j = 0; j < 4; j++) {
            float v0 = s[g2 * 8 + j * 2]     * inv;
            float v1 = s[g2 * 8 + j * 2 + 1] * inv;
            split2(v0, v1, hh[j], ll[j]);
        }
        *(uint4*)(ph + g2 * 8) = make_uint4(hh[0], hh[1], hh[2], hh[3]);
        *(uint4*)(pl + g2 * 8) = make_uint4(ll[0], ll[1], ll[2], ll[3]);
    }
}

// ---------------- query-grid pooling (bf16 hi/lo) --------------------------
__global__ void pool_P1_bf()
{
    const int idx = blockIdx.x * 256 + threadIdx.x;   // 4,194,304 (uint2 units)
    const int b  = idx >> 20;
    const int q1 = (idx >> 10) & 1023;
    const int k4 = idx & 1023;
    const int h2 = q1 >> 5, w2 = q1 & 31;
    const size_t r = (size_t)b * 4096 + (h2 * 2) * 64 + w2 * 2;
    const uint2* ph = (const uint2*)g_Ph + r * 1024 + k4;
    const uint2* pl = (const uint2*)g_Pl + r * 1024 + k4;
    float4 acc = make_float4(0.f, 0.f, 0.f, 0.f);
#pragma unroll
    for (int dr = 0; dr < 4; dr++) {
        const int off = ((dr >> 1) * 64 + (dr & 1)) * 1024;
        uint2 uh = ph[off], ul = pl[off];
        float2 f0 = rec2(uh.x, ul.x), f1 = rec2(uh.y, ul.y);
        acc.x += f0.x; acc.y += f0.y; acc.z += f1.x; acc.w += f1.y;
    }
    uint32_t h0, l0, h1, l1;
    split2(acc.x * 0.25f, acc.y * 0.25f, h0, l0);
    split2(acc.z * 0.25f, acc.w * 0.25f, h1, l1);
    const size_t o = ((size_t)b * 1024 + q1) * 1024 + k4;
    ((uint2*)g_P1h)[o] = make_uint2(h0, h1);
    ((uint2*)g_P1l)[o] = make_uint2(l0, l1);
}

__global__ void pool_P2_bf()
{
    const int idx = blockIdx.x * 256 + threadIdx.x;   // 1,048,576
    const int b  = idx >> 18;
    const int q2 = (idx >> 10) & 255;
    const int k4 = idx & 1023;
    const int h4 = q2 >> 4, w4 = q2 & 15;
    const size_t r = (size_t)b * 1024 + (h4 * 2) * 32 + w4 * 2;
    const uint2* ph = (const uint2*)g_P1h + r * 1024 + k4;
    const uint2* pl = (const uint2*)g_P1l + r * 1024 + k4;
    float4 acc = make_float4(0.f, 0.f, 0.f, 0.f);
#pragma unroll
    for (int dr = 0; dr < 4; dr++) {
        const int off = ((dr >> 1) * 32 + (dr & 1)) * 1024;
        uint2 uh = ph[off], ul = pl[off];
        float2 f0 = rec2(uh.x, ul.x), f1 = rec2(uh.y, ul.y);
        acc.x += f0.x; acc.y += f0.y; acc.z += f1.x; acc.w += f1.y;
    }
    uint32_t h0, l0, h1, l1;
    split2(acc.x * 0.25f, acc.y * 0.25f, h0, l0);
    split2(acc.z * 0.25f, acc.w * 0.25f, h1, l1);
    const size_t o = ((size_t)b * 256 + q2) * 1024 + k4;
    ((uint2*)g_P2h)[o] = make_uint2(h0, h1);
    ((uint2*)g_P2l)[o] = make_uint2(l0, l1);
}

// ---------------- V^T [b][576][4096] bf16 hi/lo ----------------------------
__global__ void build_Vt(const float* __restrict__ ref,
                         const float* __restrict__ o1,
                         const float* __restrict__ o2)
{
    const int idx = blockIdx.x * 256 + threadIdx.x;   // 4,718,592 (pairs)
    const int k2 = idx & 2047;
    const int v  = (idx >> 11) % 576;
    const int b  = idx / (576 * 2048);
    const int k  = k2 * 2;
    const int h = k >> 6, w = k & 63;
    float f0, f1;
    if (v < 192) {
        const float* s = ref + (((size_t)b * 192 + v) << 12) + k;
        f0 = s[0]; f1 = s[1];
    } else if (v < 384) {
        const float* s = o1 + (((size_t)b * 192 + (v - 192)) << 10) + (h >> 1) * 32;
        f0 = 0.25f * s[w >> 1];
        f1 = f0;                                   // w even -> same source
    } else {
        const float* s = o2 + (((size_t)b * 192 + (v - 384)) << 8) + (h >> 2) * 16;
        f0 = 0.0625f * s[w >> 2];
        f1 = f0;
    }
    uint32_t hh, ll;
    split2(f0, f1, hh, ll);
    const size_t o = ((size_t)b * 576 + v) * 2048 + k2;
    ((uint32_t*)g_Vth)[o] = hh;
    ((uint32_t*)g_Vtl)[o] = ll;
}

// ---------------- PV GEMM via mma.sync -> final outputs --------------------
// CTA tile 64q x 192c (full level width), 8 warps (2x4), warp tile 32x48.
// grid (1, 84, 4): y<64 level0, y<80 level1, else level2.
__global__ void __launch_bounds__(256, 2)
gemm_pv_mma(float* __restrict__ out)
{
    __shared__ __nv_bfloat16 sA[2][2][64 * 24];    // 12 KB
    __shared__ __nv_bfloat16 sB[2][2][192 * 24];   // 36 KB

    const int y = blockIdx.y, b = blockIdx.z;
    const __nv_bfloat16 *APh, *APl; int Mq, voff, mb; float* ob;
    if (y < 64)      { APh = g_Ph;  APl = g_Pl;  Mq = 4096; voff = 0;   ob = out;           mb = y; }
    else if (y < 80) { APh = g_P1h; APl = g_P1l; Mq = 1024; voff = 192; ob = out + 3145728; mb = y - 64; }
    else             { APh = g_P2h; APl = g_P2l; Mq = 256;  voff = 384; ob = out + 3932160; mb = y - 80; }
    const int m0 = mb * 64;
    const uint4* Agh = (const uint4*)(APh + ((size_t)b * Mq + m0) * 4096);
    const uint4* Agl = (const uint4*)(APl + ((size_t)b * Mq + m0) * 4096);
    const uint4* Bgh = (const uint4*)(g_Vth + ((size_t)(b * 576) + voff) * 4096);
    const uint4* Bgl = (const uint4*)(g_Vtl + ((size_t)(b * 576) + voff) * 4096);
    float* Ob = ob + (size_t)b * 192 * Mq;

    const int tid = threadIdx.x, wid = tid >> 5, lid = tid & 31;
    const int wm = wid & 1, wn = wid >> 1;

    float c[2][6][4];
#pragma unroll
    for (int i = 0; i < 2; i++)
#pragma unroll
        for (int j = 0; j < 6; j++)
#pragma unroll
            for (int k = 0; k < 4; k++) c[i][j][k] = 0.f;

    // A-load map: 1 uint4/thread (64 rows x 2 halves x hi/lo)
    const int asp = tid >> 7, aj = tid & 127, arw = aj >> 1, ahf = aj & 1;
    const uint4* Ag = asp ? Agl : Agh;

    // chunk 0
    *(uint4*)&sA[0][asp][arw * 24 + ahf * 8] = Ag[arw * 512 + ahf];
#pragma unroll
    for (int p = 0; p < 3; p++) {
        int i = p * 256 + tid;
        int sp = i >= 384;
        int j = sp ? i - 384 : i;
        int rw = j >> 1, hf = j & 1;
        *(uint4*)&sB[0][sp][rw * 24 + hf * 8] = (sp ? Bgl : Bgh)[rw * 512 + hf];
    }
    __syncthreads();

    const int arow = (lid & 7) + ((lid >> 3) & 1) * 8;
    const int acol = ((lid >> 4) & 1) * 16;
    const int brow = (lid & 7) + ((lid >> 4) & 1) * 8;
    const int bcol = ((lid >> 3) & 1) * 16;

#pragma unroll 1
    for (int kc = 0; kc < 256; kc++) {
        const int buf = kc & 1;
        if (kc < 255) {
            const int nb = buf ^ 1, kk = (kc + 1) * 2;
            *(uint4*)&sA[nb][asp][arw * 24 + ahf * 8] = Ag[arw * 512 + kk + ahf];
#pragma unroll
            for (int p = 0; p < 3; p++) {
                int i = p * 256 + tid;
                int sp = i >= 384;
                int j = sp ? i - 384 : i;
                int rw = j >> 1, hf = j & 1;
                *(uint4*)&sB[nb][sp][rw * 24 + hf * 8] = (sp ? Bgl : Bgh)[rw * 512 + kk + hf];
            }
        }

        uint32_t Ah[2][4], Bh[6][2];
#pragma unroll
        for (int mf = 0; mf < 2; mf++)
            ldm4(Ah[mf], smem_u32(&sA[buf][0][(wm * 32 + mf * 16 + arow) * 24]) + acol);
#pragma unroll
        for (int nf2 = 0; nf2 < 3; nf2++) {
            uint32_t r[4];
            ldm4(r, smem_u32(&sB[buf][0][(wn * 48 + nf2 * 16 + brow) * 24]) + bcol);
            Bh[nf2 * 2][0] = r[0]; Bh[nf2 * 2][1] = r[1];
            Bh[nf2 * 2 + 1][0] = r[2]; Bh[nf2 * 2 + 1][1] = r[3];
        }
#pragma unroll
        for (int mf = 0; mf < 2; mf++)
#pragma unroll
            for (int nf = 0; nf < 6; nf++)
                mma16816(c[mf][nf], Ah[mf], Bh[nf]);

        uint32_t Bl[6][2];
#pragma unroll
        for (int nf2 = 0; nf2 < 3; nf2++) {
            uint32_t r[4];
            ldm4(r, smem_u32(&sB[buf][1][(wn * 48 + nf2 * 16 + brow) * 24]) + bcol);
            Bl[nf2 * 2][0] = r[0]; Bl[nf2 * 2][1] = r[1];
            Bl[nf2 * 2 + 1][0] = r[2]; Bl[nf2 * 2 + 1][1] = r[3];
        }
#pragma unroll
        for (int mf = 0; mf < 2; mf++)
#pragma unroll
            for (int nf = 0; nf < 6; nf++)
                mma16816(c[mf][nf], Ah[mf], Bl[nf]);

        uint32_t Al[2][4];
#pragma unroll
        for (int mf = 0; mf < 2; mf++)
            ldm4(Al[mf], smem_u32(&sA[buf][1][(wm * 32 + mf * 16 + arow) * 24]) + acol);
#pragma unroll
        for (int mf = 0; mf < 2; mf++)
#pragma unroll
            for (int nf = 0; nf < 6; nf++)
                mma16816(c[mf][nf], Al[mf], Bh[nf]);
        __syncthreads();
    }

    // epilogue: out[c][q] transposed; 8-lane groups write 32B sectors
    const int g = lid >> 2;
    const int colq = (lid & 3) * 2;
#pragma unroll
    for (int mf = 0; mf < 2; mf++) {
        const int q = m0 + wm * 32 + mf * 16 + g;
#pragma unroll
        for (int nf = 0; nf < 6; nf++) {
            const int cc = wn * 48 + nf * 8 + colq;
            Ob[(size_t)cc * Mq + q]           = c[mf][nf][0];
            Ob[(size_t)(cc + 1) * Mq + q]     = c[mf][nf][1];
            Ob[(size_t)cc * Mq + q + 8]       = c[mf][nf][2];
            Ob[(size_t)(cc + 1) * Mq + q + 8] = c[mf][nf][3];
        }
    }
}

// ---------------------------------------------------------------------------
extern "C" void kernel_launch(void* const* d_in, const int* in_sizes, int n_in,
                              void* d_out, int out_size)
{
    (void)in_sizes; (void)n_in; (void)out_size;
    const float* fd1 = (const float*)d_in[0];
    const float* fd2 = (const float*)d_in[1];
    const float* ref = (const float*)d_in[2];
    const float* o1  = (const float*)d_in[3];
    const float* o2  = (const float*)d_in[4];
    const float* tw1 = (const float*)d_in[5];
    const float* tb1 = (const float*)d_in[6];
    const float* tw2 = (const float*)d_in[7];
    const float* tb2 = (const float*)d_in[8];
    const float* pw1 = (const float*)d_in[9];
    const float* pb1 = (const float*)d_in[10];
    const float* pw2 = (const float*)d_in[11];
    const float* pb2 = (const float*)d_in[12];
    float* out = (float*)d_out;

    float *t, *f1, *f2;
    cudaGetSymbolAddress((void**)&t,  g_t);
    cudaGetSymbolAddress((void**)&f1, g_f1);
    cudaGetSymbolAddress((void**)&f2, g_f2);
    float* t0 = t;
    float* t1 = t + 3145728;

    repack_w<<<5184, 256>>>(tw1, tw2, pw1, pw2);

    conv_gemm<<<dim3(3, 32, 8), 256>>>(fd1, fd2, nullptr, nullptr, 0, 2, tb1, pb1, t0, t1);
    conv_gemm<<<dim3(3, 32, 8), 256>>>(t0, t1, fd1, fd2, 1, 3, tb2, pb2, f1, f2);

    pack_bf16<<<dim3(32, 12, 8), 256>>>(f1, f2);
    gemm_corr_mma<<<dim3(64, 32, 4), 128>>>();
    softmax_rows_bf<<<16384, 256>>>();
    pool_P1_bf<<<16384, 256>>>();
    pool_P2_bf<<<4096, 256>>>();
    build_Vt<<<18432, 256>>>(ref, o1, o2);
    gemm_pv_mma<<<dim3(1, 84, 4), 256>>>(out);
}